// round 13
// baseline (speedup 1.0000x reference)
#include <cuda_runtime.h>
#include <math_constants.h>

// Problem shape (fixed by the benchmark)
#define BB   16
#define KC   5
#define NP   4096
#define DD   1024
#define KNN  9

#define BLK_X 32               // blocks per batch (all producers); 512 total, one wave @4/SM
#define RPG   2                // rows per unit
#define UPW   8                // units per warp (8 warps * 8 units * 2 rows = 128 rows)
#define ROWS_PER_BLK 128
#define NCAND (BLK_X * KNN)    // 288 candidates per (b,k)

// -------- scratch (no device allocation allowed -> __device__ globals) ------
__device__ float2   g_cand[BB * KC * NCAND];  // (val, idx-as-float-bits) 184 KB
__device__ float    g_invnorm[BB * NP];       // 1/||patch||             256 KB
__device__ unsigned g_count[BB];              // producer arrivals (0-init; reset in-kernel)
__device__ unsigned g_done[BB];               // consumer completions (0-init; reset in-kernel)

// ============================================================================
// Consumer tail (noinline: isolate its registers from the producer mainloop).
// Merges the 288 candidates of (b,k) -> global top-9, gathers the output row.
// ============================================================================
static __device__ __noinline__ void consumer_path(
    const float* __restrict__ patches, float* __restrict__ out,
    int b, int k, float* s_v, int* s_i, int* s_top, float* s_inv)
{
    const int tid  = threadIdx.x;
    const int lane = tid & 31;
    const int bk   = b * KC + k;

    // wait for all 32 producers of this batch
    if (tid == 0) {
        while (*(volatile unsigned*)&g_count[b] < BLK_X) __nanosleep(200);
    }
    __syncthreads();
    __threadfence();                        // acquire producers' writes

    const float2* cand = g_cand + (size_t)bk * NCAND;
    for (int t = tid; t < NCAND; t += 256) {
        const float2 c = cand[t];
        s_v[t] = c.x;
        s_i[t] = __float_as_int(c.y);
    }
    __syncthreads();

    if (tid < 32) {
        // lane holds slots lane + s*32, s = 0..8 (register resident)
        float v[9]; int x[9];
        #pragma unroll
        for (int s = 0; s < 9; s++) {
            const int g = lane + s * 32;
            v[s] = s_v[g]; x[s] = s_i[g];
        }
        for (int it = 0; it < KNN; it++) {
            float bv = -CUDART_INF_F; int bi = NP; int bs = 0;
            #pragma unroll
            for (int s = 0; s < 9; s++)
                if (v[s] > bv || (v[s] == bv && x[s] < bi)) { bv = v[s]; bi = x[s]; bs = s; }
            int blane = lane;
            #pragma unroll
            for (int o = 16; o; o >>= 1) {
                const float ov = __shfl_xor_sync(0xffffffffu, bv, o);
                const int   oi = __shfl_xor_sync(0xffffffffu, bi, o);
                const int   os = __shfl_xor_sync(0xffffffffu, bs, o);
                const int   ol = __shfl_xor_sync(0xffffffffu, blane, o);
                if (ov > bv || (ov == bv && oi < bi)) { bv = ov; bi = oi; bs = os; blane = ol; }
            }
            if (lane == blane) v[bs] = -CUDART_INF_F;        // mask winner
            if (lane == 0) s_top[it] = bi;
        }
        if (lane < KNN)
            s_inv[lane] = g_invnorm[(size_t)b * NP + s_top[lane]] * (1.0f / (float)KNN);
    }
    __syncthreads();

    // gather: each thread owns one float4 of the D=1024 output
    float4 acc = make_float4(0.f, 0.f, 0.f, 0.f);
    #pragma unroll
    for (int i = 0; i < KNN; i++) {
        const float4 v = ((const float4*)(patches +
                          ((size_t)b * NP + s_top[i]) * DD))[tid];
        const float sc = s_inv[i];
        acc.x = fmaf(v.x, sc, acc.x);
        acc.y = fmaf(v.y, sc, acc.y);
        acc.z = fmaf(v.z, sc, acc.z);
        acc.w = fmaf(v.w, sc, acc.w);
    }
    ((float4*)out)[(size_t)bk * (DD / 4) + tid] = acc;

    // completion + reset for graph-replay determinism (5th consumer resets)
    __syncthreads();
    if (tid == 0) {
        __threadfence();
        const unsigned old = atomicAdd(&g_done[b], 1u);
        if (old == KC - 1) {
            *(volatile unsigned*)&g_count[b] = 0u;
            __threadfence();
            *(volatile unsigned*)&g_done[b] = 0u;
        }
    }
}

// ============================================================================
// Fused kernel. grid (32,16), 256 threads, one wave, ALL blocks produce
// (perfect balance); blocks bx<5 then also consume for cue k=bx.
// Producer = R7-proven streaming pass (268 MB once -> memory bound) +
// block-local top-9 per cue. Cue used RAW (positive row-scalar -> identical
// top-9 set; output involves only normalized patches).
// ============================================================================
__global__ void __launch_bounds__(256, 4) fused_kernel(const float* __restrict__ patches,
                                                       const float* __restrict__ cue,
                                                       float* __restrict__ out) {
    const int b = blockIdx.y;
    const int bx = blockIdx.x;

    __shared__ float4 s_cue[KC * DD / 4];        // 20 KB (raw cue)
    __shared__ float  s_s[KC][ROWS_PER_BLK];     // 2.5 KB block-local cosines
    __shared__ float  s_v[NCAND];                // consumer: candidate values
    __shared__ int    s_i[NCAND];                // consumer: candidate indices
    __shared__ int    s_top[KNN];
    __shared__ float  s_inv[KNN];

    const int warp = threadIdx.x >> 5;
    const int lane = threadIdx.x & 31;
    const int tid  = threadIdx.x;

    // ==================== PRODUCER (R7 sims, unchanged) ====================
    {
        const float4* src = (const float4*)(cue + (size_t)b * KC * DD);
        for (int i = tid; i < KC * DD / 4; i += 256) s_cue[i] = src[i];
    }
    __syncthreads();

    const float4* pbase = (const float4*)(patches + (size_t)b * NP * DD);
    const int u0 = bx * (ROWS_PER_BLK / RPG);    // first unit of this block

    const float4* p = pbase + (size_t)(u0 + warp) * RPG * (DD / 4);
    float4 v0[RPG], v1[RPG], v2[RPG];
    #pragma unroll
    for (int rr = 0; rr < RPG; rr++) {
        v0[rr] = __ldcs(&p[lane + rr * (DD / 4)]);
        v1[rr] = __ldcs(&p[lane + 32 + rr * (DD / 4)]);
    }

    for (int m = 0; m < UPW; m++) {
        const bool has_next = (m < UPW - 1);
        const float4* pn = p + 8 * RPG * (DD / 4);    // next unit (stride 8)

        float acc[RPG][6];
        #pragma unroll
        for (int rr = 0; rr < RPG; rr++)
            #pragma unroll
            for (int i = 0; i < 6; i++) acc[rr][i] = 0.f;

        #pragma unroll
        for (int j = 0; j < 8; j++) {
            if (j < 6) {
                const int offn = lane + (j + 2) * 32;
                #pragma unroll
                for (int rr = 0; rr < RPG; rr++)
                    v2[rr] = __ldcs(&p[offn + rr * (DD / 4)]);
            } else if (has_next) {
                const int offn = lane + (j - 6) * 32;
                #pragma unroll
                for (int rr = 0; rr < RPG; rr++)
                    v2[rr] = __ldcs(&pn[offn + rr * (DD / 4)]);
            }

            const int off = lane + j * 32;
            #pragma unroll
            for (int rr = 0; rr < RPG; rr++) {
                acc[rr][5] = fmaf(v0[rr].x, v0[rr].x, acc[rr][5]);
                acc[rr][5] = fmaf(v0[rr].y, v0[rr].y, acc[rr][5]);
                acc[rr][5] = fmaf(v0[rr].z, v0[rr].z, acc[rr][5]);
                acc[rr][5] = fmaf(v0[rr].w, v0[rr].w, acc[rr][5]);
            }
            #pragma unroll
            for (int k = 0; k < KC; k++) {
                const float4 c = s_cue[k * (DD / 4) + off];
                #pragma unroll
                for (int rr = 0; rr < RPG; rr++) {
                    acc[rr][k] = fmaf(v0[rr].x, c.x, acc[rr][k]);
                    acc[rr][k] = fmaf(v0[rr].y, c.y, acc[rr][k]);
                    acc[rr][k] = fmaf(v0[rr].z, c.z, acc[rr][k]);
                    acc[rr][k] = fmaf(v0[rr].w, c.w, acc[rr][k]);
                }
            }
            #pragma unroll
            for (int rr = 0; rr < RPG; rr++) { v0[rr] = v1[rr]; v1[rr] = v2[rr]; }
        }

        const int lrow0 = (warp + m * 8) * RPG;
        #pragma unroll
        for (int rr = 0; rr < RPG; rr++) {
            #pragma unroll
            for (int i = 0; i < 6; i++)
                #pragma unroll
                for (int o = 16; o; o >>= 1)
                    acc[rr][i] += __shfl_xor_sync(0xffffffffu, acc[rr][i], o);
            const float inv = rsqrtf(fmaxf(acc[rr][5], 1e-24f));
            float val = acc[rr][0];
            if (lane == 1) val = acc[rr][1];
            if (lane == 2) val = acc[rr][2];
            if (lane == 3) val = acc[rr][3];
            if (lane == 4) val = acc[rr][4];
            if (lane < 5)
                s_s[lane][lrow0 + rr] = val * inv;
            else if (lane == 5)
                g_invnorm[(size_t)b * NP + bx * ROWS_PER_BLK + lrow0 + rr] = inv;
        }

        if (has_next) p = pn;
    }
    __syncthreads();

    // Block-local top-9 per cue: warp k selects from s_s[k][0..128).
    if (warp < KC) {
        const int k = warp;
        float v4[4];
        const int base = lane * 4;
        #pragma unroll
        for (int i = 0; i < 4; i++) v4[i] = s_s[k][base + i];

        float2* cand = g_cand + ((size_t)(b * KC + k) * BLK_X + bx) * KNN;
        for (int it = 0; it < KNN; it++) {
            float bv = -CUDART_INF_F; int bi = ROWS_PER_BLK;
            #pragma unroll
            for (int i = 0; i < 4; i++)
                if (v4[i] > bv) { bv = v4[i]; bi = base + i; }   // lowest idx on tie
            #pragma unroll
            for (int o = 16; o; o >>= 1) {
                const float ov = __shfl_xor_sync(0xffffffffu, bv, o);
                const int   oi = __shfl_xor_sync(0xffffffffu, bi, o);
                if (ov > bv || (ov == bv && oi < bi)) { bv = ov; bi = oi; }
            }
            if ((bi >> 2) == lane) v4[bi & 3] = -CUDART_INF_F;   // mask winner
            if (lane == 0)
                cand[it] = make_float2(bv, __int_as_float(bx * ROWS_PER_BLK + bi));
        }
    }

    // release our cand/invnorm writes, then signal arrival
    __syncthreads();
    __threadfence();
    if (tid == 0) atomicAdd(&g_count[b], 1u);

    // ==================== CONSUMER (blocks bx < 5 only) ====================
    if (bx < KC)
        consumer_path(patches, out, b, bx, s_v, s_i, s_top, s_inv);
}

// ============================================================================
extern "C" void kernel_launch(void* const* d_in, const int* in_sizes, int n_in,
                              void* d_out, int out_size) {
    const float* cue     = (const float*)d_in[0];
    const float* patches = (const float*)d_in[1];
    // defensive: identify by element count (cue = 81920, patches = 67108864)
    if (n_in >= 2 && in_sizes[0] > in_sizes[1]) {
        cue     = (const float*)d_in[1];
        patches = (const float*)d_in[0];
    }

    dim3 g1(BLK_X, BB);
    fused_kernel<<<g1, 256>>>(patches, cue, (float*)d_out);
}

// round 14
// speedup vs baseline: 1.0688x; 1.0688x over previous
#include <cuda_runtime.h>
#include <math_constants.h>

// Problem shape (fixed by the benchmark)
#define BB   16
#define KC   5
#define NP   4096
#define DD   1024
#define KNN  9

#define BLK_X 32               // sims blocks per batch (512 total, one wave @4/SM)
#define RPG   2                // rows per unit
#define UPW   8                // units per warp
#define ROWS_PER_BLK 128
#define NCAND (BLK_X * KNN)    // 288 candidates per (b,k)
#define QD    4                // D-quarters in the gather kernel

// -------- scratch (no device allocation allowed -> __device__ globals) ------
__device__ float2 g_cand[BB * KC * NCAND];  // (val, idx-as-float-bits) 184 KB
__device__ float  g_invnorm[BB * NP];       // 1/||patch||             256 KB

// -------- packed f32x2 helpers: ONLY the accumulators are 64-bit; loads stay
// float4. Packs via mov.b64 (consecutive float4 components can alias to a
// register pair). fma.rn.f32x2 halves FFMA-pipe time (rt2 -> effective rt1/f32).
typedef unsigned long long u64;
__device__ __forceinline__ u64 pk2(float lo, float hi) {
    u64 r;
    asm("mov.b64 %0, {%1, %2};" : "=l"(r) : "f"(lo), "f"(hi));
    return r;
}
__device__ __forceinline__ void fma2(u64& d, u64 a, u64 b) {
    asm("fma.rn.f32x2 %0, %1, %2, %0;" : "+l"(d) : "l"(a), "l"(b));
}
__device__ __forceinline__ float upk_sum(u64 p) {
    float lo, hi;
    asm("mov.b64 {%0, %1}, %2;" : "=f"(lo), "=f"(hi) : "l"(p));
    return lo + hi;
}

// ============================================================================
// Kernel 1: one pass over patches (268 MB -> memory bound) + first-level
// top-9 per 128-row partition. Cue used RAW (positive row-scalar -> identical
// top-9 set; output only involves normalized patches). Structure = proven R7;
// FMA bodies use packed f32x2 accumulators to halve FMA-pipe occupancy.
// ============================================================================
__global__ void __launch_bounds__(256, 4) sims_kernel(const float* __restrict__ patches,
                                                      const float* __restrict__ cue) {
    const int b = blockIdx.y;
    const int bx = blockIdx.x;

    __shared__ float4 s_cue[KC * DD / 4];        // 20 KB (raw cue)
    __shared__ float  s_s[KC][ROWS_PER_BLK];     // 2.5 KB block-local cosines
    {
        const float4* src = (const float4*)(cue + (size_t)b * KC * DD);
        for (int i = threadIdx.x; i < KC * DD / 4; i += 256) s_cue[i] = src[i];
    }
    __syncthreads();

    const int warp = threadIdx.x >> 5;
    const int lane = threadIdx.x & 31;
    const float4* pbase = (const float4*)(patches + (size_t)b * NP * DD);
    const int u0 = bx * (ROWS_PER_BLK / RPG);    // first unit of this block

    const float4* p = pbase + (size_t)(u0 + warp) * RPG * (DD / 4);
    float4 v[RPG], vn[RPG];
    #pragma unroll
    for (int rr = 0; rr < RPG; rr++)
        v[rr] = __ldcs(&p[lane + rr * (DD / 4)]);

    for (int m = 0; m < UPW; m++) {
        const bool has_next = (m < UPW - 1);
        const float4* pn = p + 8 * RPG * (DD / 4);    // next unit (stride 8)

        u64 acc[RPG][6];                              // packed (even,odd) sums
        #pragma unroll
        for (int rr = 0; rr < RPG; rr++)
            #pragma unroll
            for (int i = 0; i < 6; i++) acc[rr][i] = 0ull;

        #pragma unroll
        for (int j = 0; j < 8; j++) {
            // depth-1 prefetch: next chunk of this unit, or next unit's first
            if (j < 7) {
                const int offn = lane + (j + 1) * 32;
                #pragma unroll
                for (int rr = 0; rr < RPG; rr++)
                    vn[rr] = __ldcs(&p[offn + rr * (DD / 4)]);
            } else if (has_next) {
                #pragma unroll
                for (int rr = 0; rr < RPG; rr++)
                    vn[rr] = __ldcs(&pn[lane + rr * (DD / 4)]);
            }

            const int off = lane + j * 32;            // 256 float4 per row
            u64 pv01[RPG], pv23[RPG];
            #pragma unroll
            for (int rr = 0; rr < RPG; rr++) {
                pv01[rr] = pk2(v[rr].x, v[rr].y);
                pv23[rr] = pk2(v[rr].z, v[rr].w);
                fma2(acc[rr][5], pv01[rr], pv01[rr]); // self-dot
                fma2(acc[rr][5], pv23[rr], pv23[rr]);
            }
            #pragma unroll
            for (int k = 0; k < KC; k++) {
                const float4 c = s_cue[k * (DD / 4) + off];
                const u64 pc01 = pk2(c.x, c.y);
                const u64 pc23 = pk2(c.z, c.w);
                #pragma unroll
                for (int rr = 0; rr < RPG; rr++) {
                    fma2(acc[rr][k], pv01[rr], pc01);
                    fma2(acc[rr][k], pv23[rr], pc23);
                }
            }
            #pragma unroll
            for (int rr = 0; rr < RPG; rr++) v[rr] = vn[rr];
        }

        // epilogue: collapse packed pairs, butterfly -> sums in ALL lanes
        const int lrow0 = (warp + m * 8) * RPG;
        #pragma unroll
        for (int rr = 0; rr < RPG; rr++) {
            float s[6];
            #pragma unroll
            for (int i = 0; i < 6; i++) s[i] = upk_sum(acc[rr][i]);
            #pragma unroll
            for (int i = 0; i < 6; i++)
                #pragma unroll
                for (int o = 16; o; o >>= 1)
                    s[i] += __shfl_xor_sync(0xffffffffu, s[i], o);
            const float inv = rsqrtf(fmaxf(s[5], 1e-24f));
            float val = s[0];
            if (lane == 1) val = s[1];
            if (lane == 2) val = s[2];
            if (lane == 3) val = s[3];
            if (lane == 4) val = s[4];
            if (lane < 5)
                s_s[lane][lrow0 + rr] = val * inv;
            else if (lane == 5)
                g_invnorm[(size_t)b * NP + bx * ROWS_PER_BLK + lrow0 + rr] = inv;
        }

        if (has_next) p = pn;
    }
    __syncthreads();

    // Block-local top-9 per cue: warp k selects from s_s[k][0..128).
    if (warp < KC) {
        const int k = warp;
        float v4[4];
        const int base = lane * 4;
        #pragma unroll
        for (int i = 0; i < 4; i++) v4[i] = s_s[k][base + i];

        float2* cand = g_cand + ((size_t)(b * KC + k) * BLK_X + bx) * KNN;
        for (int it = 0; it < KNN; it++) {
            float bv = -CUDART_INF_F; int bi = ROWS_PER_BLK;
            #pragma unroll
            for (int i = 0; i < 4; i++)
                if (v4[i] > bv) { bv = v4[i]; bi = base + i; }   // lowest idx on tie
            #pragma unroll
            for (int o = 16; o; o >>= 1) {
                const float ov = __shfl_xor_sync(0xffffffffu, bv, o);
                const int   oi = __shfl_xor_sync(0xffffffffu, bi, o);
                if (ov > bv || (ov == bv && oi < bi)) { bv = ov; bi = oi; }
            }
            if ((bi >> 2) == lane) v4[bi & 3] = -CUDART_INF_F;   // mask winner
            if (lane == 0)
                cand[it] = make_float2(bv, __int_as_float(bx * ROWS_PER_BLK + bi));
        }
    }
}

// ============================================================================
// Kernel 2 (R11-proven): grid (QD, 80). Each block REDUNDANTLY merges the 288
// candidates of its (b,k) (deterministic), then gathers its quarter of D.
// ============================================================================
__global__ void __launch_bounds__(256) topk_kernel(const float* __restrict__ patches,
                                                   float* __restrict__ out) {
    const int q  = blockIdx.x;          // 0..3 D-quarter
    const int bk = blockIdx.y;          // 0..79
    const int b = bk / KC;
    const int tid = threadIdx.x;

    __shared__ float  s_v[NCAND];
    __shared__ int    s_i[NCAND];
    __shared__ int    s_top[KNN];
    __shared__ float  s_inv[KNN];
    __shared__ float4 s_part[3][DD / 4 / QD];   // 3 KB partials (groups 1..3)

    const float2* cand = g_cand + (size_t)bk * NCAND;
    for (int t = tid; t < NCAND; t += 256) {
        const float2 c = cand[t];
        s_v[t] = c.x;
        s_i[t] = __float_as_int(c.y);
    }
    __syncthreads();

    if (tid < 32) {
        const int lane = tid;
        float v[9]; int x[9];
        #pragma unroll
        for (int s = 0; s < 9; s++) {
            const int g = lane + s * 32;
            v[s] = s_v[g]; x[s] = s_i[g];
        }
        for (int it = 0; it < KNN; it++) {
            float bv = -CUDART_INF_F; int bi = NP; int bs = 0;
            #pragma unroll
            for (int s = 0; s < 9; s++)
                if (v[s] > bv || (v[s] == bv && x[s] < bi)) { bv = v[s]; bi = x[s]; bs = s; }
            int blane = lane;
            #pragma unroll
            for (int o = 16; o; o >>= 1) {
                const float ov = __shfl_xor_sync(0xffffffffu, bv, o);
                const int   oi = __shfl_xor_sync(0xffffffffu, bi, o);
                const int   os = __shfl_xor_sync(0xffffffffu, bs, o);
                const int   ol = __shfl_xor_sync(0xffffffffu, blane, o);
                if (ov > bv || (ov == bv && oi < bi)) { bv = ov; bi = oi; bs = os; blane = ol; }
            }
            if (lane == blane) v[bs] = -CUDART_INF_F;          // mask winner
            if (lane == 0) s_top[it] = bi;
        }
        if (lane < KNN)
            s_inv[lane] = g_invnorm[(size_t)b * NP + s_top[lane]] * (1.0f / (float)KNN);
    }
    __syncthreads();

    // Gather this block's quarter: 64 float4 columns. Group g = tid>>6 does
    // rows g, g+4 (+ row 8 for g==0); combine through smem.
    const int grp = tid >> 6;                    // 0..3
    const int cc  = tid & 63;                    // column within quarter
    const int col = q * (DD / 4 / QD) + cc;      // global float4 column

    float4 acc = make_float4(0.f, 0.f, 0.f, 0.f);
    #pragma unroll
    for (int s = 0; s < 2; s++) {
        const int i = grp + s * 4;               // rows 0..7 across groups
        const float4 v = ((const float4*)(patches + ((size_t)b * NP + s_top[i]) * DD))[col];
        const float sc = s_inv[i];
        acc.x = fmaf(v.x, sc, acc.x);
        acc.y = fmaf(v.y, sc, acc.y);
        acc.z = fmaf(v.z, sc, acc.z);
        acc.w = fmaf(v.w, sc, acc.w);
    }
    if (grp == 0) {                              // row 8
        const float4 v = ((const float4*)(patches + ((size_t)b * NP + s_top[8]) * DD))[col];
        const float sc = s_inv[8];
        acc.x = fmaf(v.x, sc, acc.x);
        acc.y = fmaf(v.y, sc, acc.y);
        acc.z = fmaf(v.z, sc, acc.z);
        acc.w = fmaf(v.w, sc, acc.w);
    }

    if (grp != 0) s_part[grp - 1][cc] = acc;
    __syncthreads();

    if (grp == 0) {
        #pragma unroll
        for (int g2 = 0; g2 < 3; g2++) {
            const float4 pz = s_part[g2][cc];
            acc.x += pz.x; acc.y += pz.y; acc.z += pz.z; acc.w += pz.w;
        }
        ((float4*)out)[(size_t)bk * (DD / 4) + col] = acc;
    }
}

// ============================================================================
extern "C" void kernel_launch(void* const* d_in, const int* in_sizes, int n_in,
                              void* d_out, int out_size) {
    const float* cue     = (const float*)d_in[0];
    const float* patches = (const float*)d_in[1];
    // defensive: identify by element count (cue = 81920, patches = 67108864)
    if (n_in >= 2 && in_sizes[0] > in_sizes[1]) {
        cue     = (const float*)d_in[1];
        patches = (const float*)d_in[0];
    }

    dim3 g1(BLK_X, BB);
    sims_kernel<<<g1, 256>>>(patches, cue);

    dim3 g2(QD, BB * KC);
    topk_kernel<<<g2, 256>>>(patches, (float*)d_out);
}

// round 15
// speedup vs baseline: 1.0728x; 1.0038x over previous
#include <cuda_runtime.h>
#include <math_constants.h>

// Problem shape (fixed by the benchmark)
#define BB   16
#define KC   5
#define NP   4096
#define DD   1024
#define KNN  9

#define BLK_X 32               // sims blocks per batch (512 total, one wave @4/SM)
#define RPG   2                // rows per unit
#define UPW   8                // units per warp
#define ROWS_PER_BLK 128
#define NCAND (BLK_X * KNN)    // 288 candidates per (b,k)
#define QD    4                // D-quarters in the gather kernel

// -------- scratch (no device allocation allowed -> __device__ globals) ------
__device__ float2 g_cand[BB * KC * NCAND];  // (val, idx-as-float-bits) 184 KB
__device__ float  g_invnorm[BB * NP];       // 1/||patch||             256 KB

// -------- packed f32x2 helpers (accumulators 64-bit; patch loads stay float4)
typedef unsigned long long u64;
__device__ __forceinline__ u64 pk2(float lo, float hi) {
    u64 r;
    asm("mov.b64 %0, {%1, %2};" : "=l"(r) : "f"(lo), "f"(hi));
    return r;
}
__device__ __forceinline__ void fma2(u64& d, u64 a, u64 b) {
    asm("fma.rn.f32x2 %0, %1, %2, %0;" : "+l"(d) : "l"(a), "l"(b));
}
__device__ __forceinline__ float upk_sum(u64 p) {
    float lo, hi;
    asm("mov.b64 {%0, %1}, %2;" : "=f"(lo), "=f"(hi) : "l"(p));
    return lo + hi;
}

// ============================================================================
// Kernel 1: one pass over patches (268 MB -> memory bound) + first-level
// top-9 per 128-row partition. Cue used RAW (positive row-scalar -> identical
// top-9 set; output only involves normalized patches). s_cue held as packed
// u64 pairs so the 5 cue operands need ZERO pack-movs per iteration.
// Fires PDL trigger at the end so the gather kernel can spin up early.
// ============================================================================
__global__ void __launch_bounds__(256, 4) sims_kernel(const float* __restrict__ patches,
                                                      const float* __restrict__ cue) {
    const int b = blockIdx.y;
    const int bx = blockIdx.x;

    __shared__ ulonglong2 s_cue[KC * DD / 4];    // 20 KB raw cue as (f32,f32) pairs
    __shared__ float      s_s[KC][ROWS_PER_BLK]; // 2.5 KB block-local cosines
    {
        const float4* src = (const float4*)(cue + (size_t)b * KC * DD);
        float4* dst = (float4*)s_cue;            // same 16B layout; lo word = .x
        for (int i = threadIdx.x; i < KC * DD / 4; i += 256) dst[i] = src[i];
    }
    __syncthreads();

    const int warp = threadIdx.x >> 5;
    const int lane = threadIdx.x & 31;
    const float4* pbase = (const float4*)(patches + (size_t)b * NP * DD);
    const int u0 = bx * (ROWS_PER_BLK / RPG);    // first unit of this block

    const float4* p = pbase + (size_t)(u0 + warp) * RPG * (DD / 4);
    float4 v[RPG], vn[RPG];
    #pragma unroll
    for (int rr = 0; rr < RPG; rr++)
        v[rr] = __ldcs(&p[lane + rr * (DD / 4)]);

    for (int m = 0; m < UPW; m++) {
        const bool has_next = (m < UPW - 1);
        const float4* pn = p + 8 * RPG * (DD / 4);    // next unit (stride 8)

        u64 acc[RPG][6];                              // packed (even,odd) sums
        #pragma unroll
        for (int rr = 0; rr < RPG; rr++)
            #pragma unroll
            for (int i = 0; i < 6; i++) acc[rr][i] = 0ull;

        #pragma unroll
        for (int j = 0; j < 8; j++) {
            // depth-1 prefetch: next chunk of this unit, or next unit's first
            if (j < 7) {
                const int offn = lane + (j + 1) * 32;
                #pragma unroll
                for (int rr = 0; rr < RPG; rr++)
                    vn[rr] = __ldcs(&p[offn + rr * (DD / 4)]);
            } else if (has_next) {
                #pragma unroll
                for (int rr = 0; rr < RPG; rr++)
                    vn[rr] = __ldcs(&pn[lane + rr * (DD / 4)]);
            }

            const int off = lane + j * 32;            // 256 16B-chunks per row
            u64 pv01[RPG], pv23[RPG];
            #pragma unroll
            for (int rr = 0; rr < RPG; rr++) {
                pv01[rr] = pk2(v[rr].x, v[rr].y);
                pv23[rr] = pk2(v[rr].z, v[rr].w);
                fma2(acc[rr][5], pv01[rr], pv01[rr]); // self-dot
                fma2(acc[rr][5], pv23[rr], pv23[rr]);
            }
            #pragma unroll
            for (int k = 0; k < KC; k++) {
                const ulonglong2 c2 = s_cue[k * (DD / 4) + off]; // pre-paired
                #pragma unroll
                for (int rr = 0; rr < RPG; rr++) {
                    fma2(acc[rr][k], pv01[rr], c2.x);
                    fma2(acc[rr][k], pv23[rr], c2.y);
                }
            }
            #pragma unroll
            for (int rr = 0; rr < RPG; rr++) v[rr] = vn[rr];
        }

        // epilogue: collapse packed pairs, butterfly -> sums in ALL lanes
        const int lrow0 = (warp + m * 8) * RPG;
        #pragma unroll
        for (int rr = 0; rr < RPG; rr++) {
            float s[6];
            #pragma unroll
            for (int i = 0; i < 6; i++) s[i] = upk_sum(acc[rr][i]);
            #pragma unroll
            for (int i = 0; i < 6; i++)
                #pragma unroll
                for (int o = 16; o; o >>= 1)
                    s[i] += __shfl_xor_sync(0xffffffffu, s[i], o);
            const float inv = rsqrtf(fmaxf(s[5], 1e-24f));
            float val = s[0];
            if (lane == 1) val = s[1];
            if (lane == 2) val = s[2];
            if (lane == 3) val = s[3];
            if (lane == 4) val = s[4];
            if (lane < 5)
                s_s[lane][lrow0 + rr] = val * inv;
            else if (lane == 5)
                g_invnorm[(size_t)b * NP + bx * ROWS_PER_BLK + lrow0 + rr] = inv;
        }

        if (has_next) p = pn;
    }
    __syncthreads();

    // Block-local top-9 per cue: warp k selects from s_s[k][0..128).
    if (warp < KC) {
        const int k = warp;
        float v4[4];
        const int base = lane * 4;
        #pragma unroll
        for (int i = 0; i < 4; i++) v4[i] = s_s[k][base + i];

        float2* cand = g_cand + ((size_t)(b * KC + k) * BLK_X + bx) * KNN;
        for (int it = 0; it < KNN; it++) {
            float bv = -CUDART_INF_F; int bi = ROWS_PER_BLK;
            #pragma unroll
            for (int i = 0; i < 4; i++)
                if (v4[i] > bv) { bv = v4[i]; bi = base + i; }   // lowest idx on tie
            #pragma unroll
            for (int o = 16; o; o >>= 1) {
                const float ov = __shfl_xor_sync(0xffffffffu, bv, o);
                const int   oi = __shfl_xor_sync(0xffffffffu, bi, o);
                if (ov > bv || (ov == bv && oi < bi)) { bv = ov; bi = oi; }
            }
            if ((bi >> 2) == lane) v4[bi & 3] = -CUDART_INF_F;   // mask winner
            if (lane == 0)
                cand[it] = make_float2(bv, __int_as_float(bx * ROWS_PER_BLK + bi));
        }
    }

#if __CUDA_ARCH__ >= 900
    cudaTriggerProgrammaticLaunchCompletion();   // let PDL secondary spin up
#endif
}

// ============================================================================
// Kernel 2 (R11 structure + PDL gate): grid (QD, 80). Each block REDUNDANTLY
// merges the 288 candidates of its (b,k), then gathers its quarter of D.
// ============================================================================
__global__ void __launch_bounds__(256) topk_kernel(const float* __restrict__ patches,
                                                   float* __restrict__ out) {
    const int q  = blockIdx.x;          // 0..3 D-quarter
    const int bk = blockIdx.y;          // 0..79
    const int b = bk / KC;
    const int tid = threadIdx.x;

    __shared__ float  s_v[NCAND];
    __shared__ int    s_i[NCAND];
    __shared__ int    s_top[KNN];
    __shared__ float  s_inv[KNN];
    __shared__ float4 s_part[3][DD / 4 / QD];   // 3 KB partials (groups 1..3)

#if __CUDA_ARCH__ >= 900
    cudaGridDependencySynchronize();    // wait for ALL sims blocks' results
#endif

    const float2* cand = g_cand + (size_t)bk * NCAND;
    for (int t = tid; t < NCAND; t += 256) {
        const float2 c = cand[t];
        s_v[t] = c.x;
        s_i[t] = __float_as_int(c.y);
    }
    __syncthreads();

    if (tid < 32) {
        const int lane = tid;
        float v[9]; int x[9];
        #pragma unroll
        for (int s = 0; s < 9; s++) {
            const int g = lane + s * 32;
            v[s] = s_v[g]; x[s] = s_i[g];
        }
        for (int it = 0; it < KNN; it++) {
            float bv = -CUDART_INF_F; int bi = NP; int bs = 0;
            #pragma unroll
            for (int s = 0; s < 9; s++)
                if (v[s] > bv || (v[s] == bv && x[s] < bi)) { bv = v[s]; bi = x[s]; bs = s; }
            int blane = lane;
            #pragma unroll
            for (int o = 16; o; o >>= 1) {
                const float ov = __shfl_xor_sync(0xffffffffu, bv, o);
                const int   oi = __shfl_xor_sync(0xffffffffu, bi, o);
                const int   os = __shfl_xor_sync(0xffffffffu, bs, o);
                const int   ol = __shfl_xor_sync(0xffffffffu, blane, o);
                if (ov > bv || (ov == bv && oi < bi)) { bv = ov; bi = oi; bs = os; blane = ol; }
            }
            if (lane == blane) v[bs] = -CUDART_INF_F;          // mask winner
            if (lane == 0) s_top[it] = bi;
        }
        if (lane < KNN)
            s_inv[lane] = g_invnorm[(size_t)b * NP + s_top[lane]] * (1.0f / (float)KNN);
    }
    __syncthreads();

    // Gather this block's quarter: 64 float4 columns. Group g = tid>>6 does
    // rows g, g+4 (+ row 8 for g==0); combine through smem.
    const int grp = tid >> 6;                    // 0..3
    const int cc  = tid & 63;                    // column within quarter
    const int col = q * (DD / 4 / QD) + cc;      // global float4 column

    float4 acc = make_float4(0.f, 0.f, 0.f, 0.f);
    #pragma unroll
    for (int s = 0; s < 2; s++) {
        const int i = grp + s * 4;               // rows 0..7 across groups
        const float4 v = ((const float4*)(patches + ((size_t)b * NP + s_top[i]) * DD))[col];
        const float sc = s_inv[i];
        acc.x = fmaf(v.x, sc, acc.x);
        acc.y = fmaf(v.y, sc, acc.y);
        acc.z = fmaf(v.z, sc, acc.z);
        acc.w = fmaf(v.w, sc, acc.w);
    }
    if (grp == 0) {                              // row 8
        const float4 v = ((const float4*)(patches + ((size_t)b * NP + s_top[8]) * DD))[col];
        const float sc = s_inv[8];
        acc.x = fmaf(v.x, sc, acc.x);
        acc.y = fmaf(v.y, sc, acc.y);
        acc.z = fmaf(v.z, sc, acc.z);
        acc.w = fmaf(v.w, sc, acc.w);
    }

    if (grp != 0) s_part[grp - 1][cc] = acc;
    __syncthreads();

    if (grp == 0) {
        #pragma unroll
        for (int g2 = 0; g2 < 3; g2++) {
            const float4 pz = s_part[g2][cc];
            acc.x += pz.x; acc.y += pz.y; acc.z += pz.z; acc.w += pz.w;
        }
        ((float4*)out)[(size_t)bk * (DD / 4) + col] = acc;
    }
}

// ============================================================================
extern "C" void kernel_launch(void* const* d_in, const int* in_sizes, int n_in,
                              void* d_out, int out_size) {
    const float* cue     = (const float*)d_in[0];
    const float* patches = (const float*)d_in[1];
    // defensive: identify by element count (cue = 81920, patches = 67108864)
    if (n_in >= 2 && in_sizes[0] > in_sizes[1]) {
        cue     = (const float*)d_in[1];
        patches = (const float*)d_in[0];
    }

    dim3 g1(BLK_X, BB);
    sims_kernel<<<g1, 256>>>(patches, cue);

    // topk with Programmatic Dependent Launch: spins up while sims drains;
    // cudaGridDependencySynchronize() inside gates correctness.
    cudaLaunchConfig_t cfg = {};
    cfg.gridDim  = dim3(QD, BB * KC);
    cfg.blockDim = dim3(256);
    cudaLaunchAttribute attrs[1];
    attrs[0].id = cudaLaunchAttributeProgrammaticStreamSerialization;
    attrs[0].val.programmaticStreamSerializationAllowed = 1;
    cfg.attrs = attrs;
    cfg.numAttrs = 1;
    cudaLaunchKernelEx(&cfg, topk_kernel, patches, (float*)d_out);
}